// round 11
// baseline (speedup 1.0000x reference)
#include <cuda_runtime.h>
#include <cuda_fp16.h>
#include <math.h>

#define MAXN   50048
#define ELLCAP 64           // max in-degree (Poisson(16); P(>=64) ~ 1e-19)

// ---- scratch (device globals; no allocation allowed) ----
__device__ float  g_deg[MAXN];                  // 1 + weighted in-degree
__device__ int    g_cnt[MAXN];                  // in-degree count
__device__ float  g_dinv[MAXN];                 // rsqrt(deg)
__device__ int2   g_epair[(long)MAXN * ELLCAP]; // {src, raw weight bits}
__device__ __half g_h[(long)MAXN * 128];        // GEMM output, pre-scaled by dinv[row]
__device__ float  g_a[(long)MAXN * 128];        // aggregated output, fp32

// load 4 consecutive halves -> float4
__device__ __forceinline__ float4 ldh4(const __half* p) {
    uint2 u = *(const uint2*)p;
    __half2 a = *(__half2*)&u.x;
    __half2 b = *(__half2*)&u.y;
    float2 fa = __half22float2(a);
    float2 fb = __half22float2(b);
    return make_float4(fa.x, fa.y, fb.x, fb.y);
}

// ---------------------------------------------------------------------------
// 1) zero: deg=1 (self-loop), cnt=0
// ---------------------------------------------------------------------------
__global__ void zero_kernel(int n) {
    int i = blockIdx.x * blockDim.x + threadIdx.x;
    if (i < n) { g_deg[i] = 1.0f; g_cnt[i] = 0; }
}

// ---------------------------------------------------------------------------
// 2) ELL fill: slot via atomic count; accumulate weighted degree
// ---------------------------------------------------------------------------
__global__ void ell_fill_kernel(const int* __restrict__ src,
                                const int* __restrict__ dst,
                                const float* __restrict__ ew, int E) {
    int e = blockIdx.x * blockDim.x + threadIdx.x;
    if (e < E) {
        int d = dst[e];
        float w = ew[e];
        int rank = atomicAdd(&g_cnt[d], 1);
        atomicAdd(&g_deg[d], w);
        if (rank < ELLCAP)
            g_epair[(size_t)d * ELLCAP + rank] = make_int2(src[e], __float_as_int(w));
    }
}

// ---------------------------------------------------------------------------
// 3) dinv = rsqrt(deg)
// ---------------------------------------------------------------------------
__global__ void dinv_kernel(int n) {
    int i = blockIdx.x * blockDim.x + threadIdx.x;
    if (i < n) g_dinv[i] = rsqrtf(g_deg[i]);
}

// ---------------------------------------------------------------------------
// SGEMM: C[M,128] = dinv[row] * (A[M,K] @ B[K,128]), stored fp16
// 128x128 tile, 256 threads, 8x8/thread
// ---------------------------------------------------------------------------
__global__ __launch_bounds__(256)
void gemm_h16(const float* __restrict__ A, const float* __restrict__ B,
              __half* __restrict__ C, int M, int K) {
    __shared__ float As[128][17];
    __shared__ float Bs[16][128];
    int tid  = threadIdx.x;
    int row0 = blockIdx.x * 128;
    int tx = tid & 15;
    int ty = tid >> 4;

    float acc[8][8];
    #pragma unroll
    for (int i = 0; i < 8; i++)
        #pragma unroll
        for (int j = 0; j < 8; j++) acc[i][j] = 0.0f;

    for (int kb = 0; kb < K; kb += 16) {
        #pragma unroll
        for (int i = 0; i < 2; i++) {
            int f  = tid * 2 + i;
            int r  = f >> 2;
            int kc = (f & 3) * 4;
            float4 v = make_float4(0.f, 0.f, 0.f, 0.f);
            int gr = row0 + r;
            if (gr < M) v = *(const float4*)&A[(size_t)gr * K + kb + kc];
            As[r][kc + 0] = v.x; As[r][kc + 1] = v.y;
            As[r][kc + 2] = v.z; As[r][kc + 3] = v.w;
        }
        #pragma unroll
        for (int i = 0; i < 2; i++) {
            int f = tid * 2 + i;
            int r = f >> 5;
            int c = (f & 31) * 4;
            *(float4*)&Bs[r][c] = *(const float4*)&B[(size_t)(kb + r) * 128 + c];
        }
        __syncthreads();

        #pragma unroll
        for (int k = 0; k < 16; k++) {
            float a[8];
            #pragma unroll
            for (int i = 0; i < 4; i++) {
                a[i]     = As[ty * 4 + i][k];
                a[i + 4] = As[64 + ty * 4 + i][k];
            }
            float4 b0 = *(const float4*)&Bs[k][tx * 4];
            float4 b1 = *(const float4*)&Bs[k][64 + tx * 4];
            float b[8] = {b0.x, b0.y, b0.z, b0.w, b1.x, b1.y, b1.z, b1.w};
            #pragma unroll
            for (int i = 0; i < 8; i++)
                #pragma unroll
                for (int j = 0; j < 8; j++)
                    acc[i][j] = fmaf(a[i], b[j], acc[i][j]);
        }
        __syncthreads();
    }

    #pragma unroll
    for (int half = 0; half < 2; half++) {
        #pragma unroll
        for (int i = 0; i < 4; i++) {
            int gr = row0 + half * 64 + ty * 4 + i;
            if (gr < M) {
                int r = half * 4 + i;
                float di = g_dinv[gr];            // fold dinv[row] into store
                __half2 h0 = __floats2half2_rn(di * acc[r][0], di * acc[r][1]);
                __half2 h1 = __floats2half2_rn(di * acc[r][2], di * acc[r][3]);
                __half2 h2 = __floats2half2_rn(di * acc[r][4], di * acc[r][5]);
                __half2 h3 = __floats2half2_rn(di * acc[r][6], di * acc[r][7]);
                uint2 u0; u0.x = *(unsigned*)&h0; u0.y = *(unsigned*)&h1;
                uint2 u1; u1.x = *(unsigned*)&h2; u1.y = *(unsigned*)&h3;
                *(uint2*)&C[(size_t)gr * 128 + tx * 4]      = u0;
                *(uint2*)&C[(size_t)gr * 128 + 64 + tx * 4] = u1;
            }
        }
    }
}

// ---------------------------------------------------------------------------
// ELL gather aggregation over pre-scaled h' = dinv*h:
//   out = relu( dd * ( h'[d] + sum_e w_e * h'[s_e] ) + bias )
// warp per node; 8-wide batched gathers, double-buffered pair loads
// ---------------------------------------------------------------------------
__global__ __launch_bounds__(256)
void agg_ell_relu_kernel(const __half* __restrict__ h, float* __restrict__ out,
                         const float* __restrict__ bias, int n) {
    int node = blockIdx.x * 8 + (threadIdx.x >> 5);
    int lane = threadIdx.x & 31;
    if (node >= n) return;

    int off = lane * 4;
    const __half* hp = h + off;
    float4 acc = ldh4(hp + (size_t)node * 128);   // self term h'[d]

    int len = min(g_cnt[node], ELLCAP);
    size_t base = (size_t)node * ELLCAP;
    const int2 SAFE = make_int2(node, 0);         // w=0: no-op, safe address

    int2 p[8];
    #pragma unroll
    for (int k = 0; k < 8; k++)
        p[k] = (k < len) ? g_epair[base + k] : SAFE;

    for (int j = 0; j < len; j += 8) {
        uint2 d[8];
        #pragma unroll
        for (int k = 0; k < 8; k++)
            d[k] = *(const uint2*)(hp + (size_t)p[k].x * 128);
        int2 np[8];
        #pragma unroll
        for (int k = 0; k < 8; k++) {
            int idx = j + 8 + k;
            np[k] = (idx < len) ? g_epair[base + idx] : SAFE;
        }
        #pragma unroll
        for (int k = 0; k < 8; k++) {
            float nm = __int_as_float(p[k].y);
            __half2 a = *(__half2*)&d[k].x;
            __half2 b = *(__half2*)&d[k].y;
            float2 fa = __half22float2(a);
            float2 fb = __half22float2(b);
            acc.x = fmaf(nm, fa.x, acc.x);
            acc.y = fmaf(nm, fa.y, acc.y);
            acc.z = fmaf(nm, fb.x, acc.z);
            acc.w = fmaf(nm, fb.y, acc.w);
        }
        #pragma unroll
        for (int k = 0; k < 8; k++) p[k] = np[k];
    }

    float dd = g_dinv[node];
    float4 bv = *(const float4*)(bias + off);
    acc.x = fmaxf(fmaf(dd, acc.x, bv.x), 0.f);
    acc.y = fmaxf(fmaf(dd, acc.y, bv.y), 0.f);
    acc.z = fmaxf(fmaf(dd, acc.z, bv.z), 0.f);
    acc.w = fmaxf(fmaf(dd, acc.w, bv.w), 0.f);
    *(float4*)(out + (size_t)node * 128 + off) = acc;
}

// ---------------------------------------------------------------------------
// Fused: layer-3 aggregation + bias + ReLU + fc(128->10) + softmax
// ---------------------------------------------------------------------------
__global__ __launch_bounds__(256)
void agg_fc_softmax_kernel(const __half* __restrict__ h,
                           const float* __restrict__ bias,
                           const float* __restrict__ fcw,
                           const float* __restrict__ fcb,
                           float* __restrict__ out, int n) {
    __shared__ float wsh[128 * 10];
    for (int i = threadIdx.x; i < 1280; i += 256) wsh[i] = fcw[i];
    __syncthreads();

    int node = blockIdx.x * 8 + (threadIdx.x >> 5);
    int lane = threadIdx.x & 31;
    if (node >= n) return;

    int off = lane * 4;
    const __half* hp = h + off;
    float4 acc = ldh4(hp + (size_t)node * 128);

    int len = min(g_cnt[node], ELLCAP);
    size_t base = (size_t)node * ELLCAP;
    const int2 SAFE = make_int2(node, 0);

    int2 p[8];
    #pragma unroll
    for (int k = 0; k < 8; k++)
        p[k] = (k < len) ? g_epair[base + k] : SAFE;

    for (int j = 0; j < len; j += 8) {
        uint2 d[8];
        #pragma unroll
        for (int k = 0; k < 8; k++)
            d[k] = *(const uint2*)(hp + (size_t)p[k].x * 128);
        int2 np[8];
        #pragma unroll
        for (int k = 0; k < 8; k++) {
            int idx = j + 8 + k;
            np[k] = (idx < len) ? g_epair[base + idx] : SAFE;
        }
        #pragma unroll
        for (int k = 0; k < 8; k++) {
            float nm = __int_as_float(p[k].y);
            __half2 a = *(__half2*)&d[k].x;
            __half2 b = *(__half2*)&d[k].y;
            float2 fa = __half22float2(a);
            float2 fb = __half22float2(b);
            acc.x = fmaf(nm, fa.x, acc.x);
            acc.y = fmaf(nm, fa.y, acc.y);
            acc.z = fmaf(nm, fb.x, acc.z);
            acc.w = fmaf(nm, fb.y, acc.w);
        }
        #pragma unroll
        for (int k = 0; k < 8; k++) p[k] = np[k];
    }

    float dd = g_dinv[node];
    float4 bv = *(const float4*)(bias + off);
    float f0 = fmaxf(fmaf(dd, acc.x, bv.x), 0.f);
    float f1 = fmaxf(fmaf(dd, acc.y, bv.y), 0.f);
    float f2 = fmaxf(fmaf(dd, acc.z, bv.z), 0.f);
    float f3 = fmaxf(fmaf(dd, acc.w, bv.w), 0.f);

    float pr[10];
    #pragma unroll
    for (int c = 0; c < 10; c++) {
        pr[c] = f0 * wsh[(off + 0) * 10 + c]
              + f1 * wsh[(off + 1) * 10 + c]
              + f2 * wsh[(off + 2) * 10 + c]
              + f3 * wsh[(off + 3) * 10 + c];
    }
    #pragma unroll
    for (int s = 16; s > 0; s >>= 1)
        #pragma unroll
        for (int c = 0; c < 10; c++)
            pr[c] += __shfl_xor_sync(0xffffffffu, pr[c], s);

    if (lane == 0) {
        float m = -1e30f;
        #pragma unroll
        for (int c = 0; c < 10; c++) { pr[c] += fcb[c]; m = fmaxf(m, pr[c]); }
        float sum = 0.f;
        #pragma unroll
        for (int c = 0; c < 10; c++) { pr[c] = __expf(pr[c] - m); sum += pr[c]; }
        float inv = 1.0f / sum;
        #pragma unroll
        for (int c = 0; c < 10; c++) out[(size_t)node * 10 + c] = pr[c] * inv;
    }
}

// ---------------------------------------------------------------------------
extern "C" void kernel_launch(void* const* d_in, const int* in_sizes, int n_in,
                              void* d_out, int out_size) {
    const float* x   = (const float*)d_in[0];
    const int*   ei  = (const int*)  d_in[1];
    const float* ew  = (const float*)d_in[2];
    const float* W1  = (const float*)d_in[3];
    const float* b1  = (const float*)d_in[4];
    const float* W2  = (const float*)d_in[5];
    const float* b2  = (const float*)d_in[6];
    const float* W3  = (const float*)d_in[7];
    const float* b3  = (const float*)d_in[8];
    const float* fcw = (const float*)d_in[9];
    const float* fcb = (const float*)d_in[10];
    float* out = (float*)d_out;

    int E = in_sizes[2];
    int n = in_sizes[0] / 256;
    const int* src = ei;
    const int* dst = ei + E;

    int nb_n = (n + 255) / 256;
    int nb_e = (E + 255) / 256;
    int nb_g = (n + 127) / 128;
    int nb_w = (n + 7) / 8;

    zero_kernel<<<nb_n, 256>>>(n);                                   // 1
    ell_fill_kernel<<<nb_e, 256>>>(src, dst, ew, E);                 // 2
    dinv_kernel<<<nb_n, 256>>>(n);                                   // 3
    gemm_h16<<<nb_g, 256>>>(x, W1, g_h, n, 256);                     // 4 <- profiled

    agg_ell_relu_kernel<<<nb_w, 256>>>(g_h, g_a, b1, n);             // 5
    gemm_h16<<<nb_g, 256>>>(g_a, W2, g_h, n, 128);                   // 6
    agg_ell_relu_kernel<<<nb_w, 256>>>(g_h, g_a, b2, n);             // 7
    gemm_h16<<<nb_g, 256>>>(g_a, W3, g_h, n, 128);                   // 8
    agg_fc_softmax_kernel<<<nb_w, 256>>>(g_h, b3, fcw, fcb, out, n); // 9
}